// round 13
// baseline (speedup 1.0000x reference)
#include <cuda_runtime.h>
#include <cuda_fp16.h>
#include <cstdint>

#define Bn 32
#define HWn 56
#define NPX 3136

// staged weights: [b][ocg2][chunk16] blocks of [tap9][ocl128][icl16] fp16 (iclS swizzled)
__device__ __half g_wH[(size_t)Bn * 2 * 16 * 18432];
// staged input: [b][yslot58][xslot64][ic256] fp16, zero-padded borders, ic^8 swizzle per xslot&4
__device__ __half g_xH[(size_t)Bn * 58 * 64 * 256];

static __device__ __forceinline__ uint32_t smem_u32(const void* p) {
    uint32_t a;
    asm("{ .reg .u64 t; cvta.to.shared.u64 t, %1; cvt.u32.u64 %0, t; }" : "=r"(a) : "l"(p));
    return a;
}
static __device__ __forceinline__ void cp16(uint32_t dst, const void* src) {
    asm volatile("cp.async.cg.shared.global [%0], [%1], 16;" :: "r"(dst), "l"(src));
}
static __device__ __forceinline__ void cp_commit() {
    asm volatile("cp.async.commit_group;" ::: "memory");
}
static __device__ __forceinline__ void ldsm4(uint32_t* r, uint32_t a) {
    asm volatile("ldmatrix.sync.aligned.m8n8.x4.shared.b16 {%0,%1,%2,%3}, [%4];"
                 : "=r"(r[0]), "=r"(r[1]), "=r"(r[2]), "=r"(r[3]) : "r"(a));
}
static __device__ __forceinline__ void mma(float* c, const uint32_t* a, uint32_t b0, uint32_t b1) {
    asm volatile("mma.sync.aligned.m16n8k16.row.col.f32.f16.f16.f32 "
                 "{%0,%1,%2,%3}, {%4,%5,%6,%7}, {%8,%9}, {%0,%1,%2,%3};"
                 : "+f"(c[0]), "+f"(c[1]), "+f"(c[2]), "+f"(c[3])
                 : "r"(a[0]), "r"(a[1]), "r"(a[2]), "r"(a[3]), "r"(b0), "r"(b1));
}

// ---------------------------------------------------------------------------
// Kernel 1: weight synthesis as split-fp16 MMA GEMM (spill-free restructure).
// Block (tap, ocl_hi, chunk, ocg): M=256 Wt rows x K=64 x N=32 batches.
// hi = fp16(64*v), lo = fp16((64*v - hi)*2048); result = (hi*hi + cross/2048)/64.
// Warp's two m-tiles processed SEQUENTIALLY (q loop) -> 32 live acc regs.
// ---------------------------------------------------------------------------
#define SA_HI 0
#define SA_LO 32768
#define SB_HI 65536
#define SB_LO 69632
#define S_OUT 73728
#define SY_TOTAL (S_OUT + 20480)

__global__ __launch_bounds__(256, 2)
void synth_kernel(const float* __restrict__ se, const float* __restrict__ Wt) {
    extern __shared__ char sy[];
    uint32_t sb = smem_u32(sy);
    unsigned short* s_out16 = reinterpret_cast<unsigned short*>(sy + S_OUT);

    int tid = threadIdx.x, lane = tid & 31, warp = tid >> 5;
    int blk = blockIdx.x;                  // 2304 = 9*8*16*2
    int tap = blk % 9; int tmp = blk / 9;
    int ocl_hi = tmp & 7; tmp >>= 3;
    int chunk = tmp & 15; int ocg = tmp >> 4;

    // --- load se -> B hi/lo smem (swizzled rows of 128B) ---
    {
        int b = tid >> 3, kq = tid & 7;
        float4 v0 = *reinterpret_cast<const float4*>(se + b * 64 + kq * 8);
        float4 v1 = *reinterpret_cast<const float4*>(se + b * 64 + kq * 8 + 4);
        float vv[8] = {v0.x, v0.y, v0.z, v0.w, v1.x, v1.y, v1.z, v1.w};
        unsigned short hs[8], ls[8];
        #pragma unroll
        for (int j = 0; j < 8; j++) {
            __half h = __float2half_rn(vv[j]);
            float r = (vv[j] - __half2float(h)) * 2048.f;
            hs[j] = __half_as_ushort(h);
            ls[j] = __half_as_ushort(__float2half_rn(r));
        }
        uint32_t addr = (uint32_t)b * 128 + (uint32_t)((kq ^ (b & 7)) * 16);
        *reinterpret_cast<uint4*>(sy + SB_HI + addr) = make_uint4(
            (uint32_t)hs[0] | ((uint32_t)hs[1] << 16), (uint32_t)hs[2] | ((uint32_t)hs[3] << 16),
            (uint32_t)hs[4] | ((uint32_t)hs[5] << 16), (uint32_t)hs[6] | ((uint32_t)hs[7] << 16));
        *reinterpret_cast<uint4*>(sy + SB_LO + addr) = make_uint4(
            (uint32_t)ls[0] | ((uint32_t)ls[1] << 16), (uint32_t)ls[2] | ((uint32_t)ls[3] << 16),
            (uint32_t)ls[4] | ((uint32_t)ls[5] << 16), (uint32_t)ls[6] | ((uint32_t)ls[7] << 16));
    }

    // --- gather Wt rows -> A hi/lo smem (scaled x64), swizzled 128B rows ---
    for (int i = tid; i < 4096; i += 256) {
        int m = i >> 4, part = i & 15;
        size_t o = ((size_t)(ocg * 128 + ocl_hi * 16 + (m >> 4)) * 256
                    + chunk * 16 + (m & 15)) * 9 + tap;
        float4 v = *reinterpret_cast<const float4*>(Wt + o * 64 + part * 4);
        float vv[4] = {v.x, v.y, v.z, v.w};
        unsigned short hs[4], ls[4];
        #pragma unroll
        for (int j = 0; j < 4; j++) {
            float s = vv[j] * 64.f;
            __half h = __float2half_rn(s);
            float r = (s - __half2float(h)) * 2048.f;
            hs[j] = __half_as_ushort(h);
            ls[j] = __half_as_ushort(__float2half_rn(r));
        }
        uint32_t addr = (uint32_t)m * 128 + (uint32_t)((((part >> 1) ^ (m & 7)) * 16) + (part & 1) * 8);
        *reinterpret_cast<uint2*>(sy + SA_HI + addr) = make_uint2(
            (uint32_t)hs[0] | ((uint32_t)hs[1] << 16), (uint32_t)hs[2] | ((uint32_t)hs[3] << 16));
        *reinterpret_cast<uint2*>(sy + SA_LO + addr) = make_uint2(
            (uint32_t)ls[0] | ((uint32_t)ls[1] << 16), (uint32_t)ls[2] | ((uint32_t)ls[3] << 16));
    }
    __syncthreads();

    int a_ml = (lane & 7) + ((lane >> 3) & 1) * 8;
    int a_kh = lane >> 4;
    int b_bl = (lane & 7) + ((lane >> 4) & 1) * 8;
    int b_kh = (lane >> 3) & 1;
    const float SC = 4.8828125e-4f, INV = 1.f / 64.f;

    // --- sequential m-tiles: 32 live acc regs per pass, no spill ---
    #pragma unroll 1
    for (int q = 0; q < 2; q++) {
        float acc1[4][4], acc2[4][4];
        #pragma unroll
        for (int n = 0; n < 4; n++)
            #pragma unroll
            for (int k = 0; k < 4; k++) { acc1[n][k] = 0.f; acc2[n][k] = 0.f; }

        int m_l = (warp * 2 + q) * 16 + a_ml;
        #pragma unroll
        for (int kt = 0; kt < 4; kt++) {
            uint32_t Ah[4], Al[4], Bh[2][4], Bl[2][4];
            uint32_t aaddr = (uint32_t)m_l * 128 + (uint32_t)(((kt * 2 + a_kh) ^ (m_l & 7)) * 16);
            ldsm4(Ah, sb + SA_HI + aaddr);
            ldsm4(Al, sb + SA_LO + aaddr);
            #pragma unroll
            for (int pr = 0; pr < 2; pr++) {
                int bl = b_bl + pr * 16;
                uint32_t baddr = (uint32_t)bl * 128 + (uint32_t)(((kt * 2 + b_kh) ^ (bl & 7)) * 16);
                ldsm4(Bh[pr], sb + SB_HI + baddr);
                ldsm4(Bl[pr], sb + SB_LO + baddr);
            }
            #pragma unroll
            for (int pr = 0; pr < 2; pr++)
                #pragma unroll
                for (int sub = 0; sub < 2; sub++) {
                    int nt = pr * 2 + sub;
                    mma(acc1[nt], Ah, Bh[pr][sub * 2], Bh[pr][sub * 2 + 1]);
                    mma(acc2[nt], Ah, Bl[pr][sub * 2], Bl[pr][sub * 2 + 1]);
                    mma(acc2[nt], Al, Bh[pr][sub * 2], Bh[pr][sub * 2 + 1]);
                }
        }

        #pragma unroll
        for (int nt = 0; nt < 4; nt++) {
            float v0 = (acc1[nt][0] + acc2[nt][0] * SC) * INV;
            float v1 = (acc1[nt][1] + acc2[nt][1] * SC) * INV;
            float v2 = (acc1[nt][2] + acc2[nt][2] * SC) * INV;
            float v3 = (acc1[nt][3] + acc2[nt][3] * SC) * INV;
            uint32_t p01 = (uint32_t)__half_as_ushort(__float2half_rn(v0))
                         | ((uint32_t)__half_as_ushort(__float2half_rn(v1)) << 16);
            uint32_t p23 = (uint32_t)__half_as_ushort(__float2half_rn(v2))
                         | ((uint32_t)__half_as_ushort(__float2half_rn(v3)) << 16);
            int m0 = (warp * 2 + q) * 16 + (lane >> 2);
            int bc = nt * 8 + (lane & 3) * 2;
            *reinterpret_cast<uint32_t*>(&s_out16[m0 * 40 + bc]) = p01;
            *reinterpret_cast<uint32_t*>(&s_out16[(m0 + 8) * 40 + bc]) = p23;
        }
    }
    __syncthreads();

    // --- flush: per b, 512B contiguous dest chunk; 4-wide gathered STG.64 ---
    size_t inner = (size_t)tap * 2048 + (size_t)ocl_hi * 256;
    for (int i = tid; i < 2048; i += 256) {
        int b = i >> 6, d4 = (i & 63) * 4;
        int ocl = d4 >> 4;
        int xorm = (ocl & 4) ? 8 : 0;
        unsigned short w[4];
        #pragma unroll
        for (int j = 0; j < 4; j++) {
            int icl = ((d4 + j) & 15) ^ xorm;
            w[j] = s_out16[(ocl * 16 + icl) * 40 + b];
        }
        size_t blko = ((size_t)(b * 2 + ocg) * 16 + chunk) * 18432;
        *reinterpret_cast<uint2*>(&reinterpret_cast<unsigned short*>(g_wH)[blko + inner + d4]) =
            make_uint2((uint32_t)w[0] | ((uint32_t)w[1] << 16),
                       (uint32_t)w[2] | ((uint32_t)w[3] << 16));
    }
}

// ---------------------------------------------------------------------------
// Kernel 2: input transpose to [b][yslot][xslot][ic] fp16, padded + swizzled
// ---------------------------------------------------------------------------
__global__ __launch_bounds__(256)
void xprep_kernel(const float* __restrict__ in) {
    extern __shared__ float s[];                     // [256][56]
    int ys = blockIdx.x, b = blockIdx.y, t = threadIdx.x;
    size_t obase = ((size_t)b * 58 + ys) * 64 * 256;

    if (ys == 0 || ys == 57) {
        uint4 z = make_uint4(0, 0, 0, 0);
        uint4* ph = reinterpret_cast<uint4*>(g_xH + obase);
        for (int i = t; i < 2048; i += 256) ph[i] = z;
        return;
    }
    int y = ys - 1;
    for (int i = t; i < 256 * 56; i += 256) {
        int ic = i / 56, x = i - ic * 56;
        s[i] = in[((size_t)b * 256 + ic) * NPX + y * 56 + x];
    }
    __syncthreads();

    int xs = t >> 2, icq = t & 3;
    bool real = (xs >= 1 && xs <= 56);
    int xsw = (xs & 4) ? 8 : 0;
    #pragma unroll
    for (int g = 0; g < 8; g++) {
        unsigned short hs[8];
        #pragma unroll
        for (int j = 0; j < 8; j++) {
            int ic_out = icq * 64 + g * 8 + j;
            int src_ic = ic_out ^ xsw;
            float v = real ? s[src_ic * 56 + (xs - 1)] : 0.f;
            hs[j] = __half_as_ushort(__float2half_rn(v));
        }
        size_t eo = obase + (size_t)xs * 256 + icq * 64 + g * 8;
        *reinterpret_cast<uint4*>(g_xH + eo) = make_uint4(
            (uint32_t)hs[0] | ((uint32_t)hs[1] << 16), (uint32_t)hs[2] | ((uint32_t)hs[3] << 16),
            (uint32_t)hs[4] | ((uint32_t)hs[5] << 16), (uint32_t)hs[6] | ((uint32_t)hs[7] << 16));
    }
}

// ---------------------------------------------------------------------------
// Kernel 3: implicit-GEMM conv, fp16 mma.sync, m32-per-warp / oc64-per-CTA.
// grid (13 pxtile256, 4 ocq, 32 b), 256 threads, 2 CTAs/SM.  (unchanged)
// ---------------------------------------------------------------------------
#define BUFB 34816
#define SMEM_TOTAL (2 * BUFB)   /* 69632 */

__global__ __launch_bounds__(256, 2)
void conv_kernel(const float* __restrict__ bias, float* __restrict__ out) {
    extern __shared__ char smem[];
    uint32_t sb = smem_u32(smem);
    int t = threadIdx.x, warp = t >> 5, lane = t & 31;
    int tile = blockIdx.x, ocq = blockIdx.y, b = blockIdx.z;
    int ocg = ocq >> 1, ohalf = ocq & 1;
    int p0 = tile * 256;
    int base = p0 / 56; if (base > 50) base = 50;

    int lrow = (lane & 7) + ((lane >> 3) & 1) * 8;
    uint32_t kh16 = (uint32_t)(lane >> 4) * 16;
    int xx[2], yrel[2];
    #pragma unroll
    for (int m = 0; m < 2; m++) {
        int pixel = p0 + warp * 32 + m * 16 + lrow;
        if (pixel >= NPX) pixel = p0;
        int yy = pixel / 56;
        xx[m] = pixel - yy * 56;
        yrel[m] = yy - base;
    }
    int oc_lane = (lane & 7) + ((lane >> 4) & 1) * 8;
    uint32_t bsw = ((uint32_t)((lane >> 3) & 1) * 16) ^ (uint32_t)((oc_lane & 4) << 2);

    const char* wsrc = (const char*)g_wH + ((size_t)(b * 2 + ocg) * 16) * 36864;
    const char* xh0 = (const char*)g_xH + ((size_t)b * 58 + base) * 32768;

    float acc[4][2][2][4];
    #pragma unroll
    for (int i = 0; i < 4; i++)
        #pragma unroll
        for (int j = 0; j < 2; j++)
            #pragma unroll
            for (int m = 0; m < 2; m++)
                #pragma unroll
                for (int k = 0; k < 4; k++) acc[i][j][m][k] = 0.f;

    auto stage = [&](int c, uint32_t bo) {
        const char* wb = wsrc + (size_t)c * 36864;
        for (int i = t; i < 1152; i += 256) {
            int tap = i >> 7, off = i & 127;
            cp16(sb + bo + tap * 2048 + off * 16,
                 wb + tap * 4096 + ohalf * 2048 + off * 16);
        }
        for (int i = t; i < 1024; i += 256) {
            int slot = i >> 7, j = i & 127, xs = j >> 1, half = j & 1;
            cp16(sb + bo + 18432 + slot * 2048 + xs * 32 + half * 16,
                 xh0 + (size_t)slot * 32768 + xs * 512 + c * 32 + half * 16);
        }
    };

    stage(0, 0);
    cp_commit();

    for (int c = 0; c < 16; c++) {
        uint32_t bo = (uint32_t)(c & 1) * BUFB;
        if (c < 15) {
            stage(c + 1, (uint32_t)((c + 1) & 1) * BUFB);
            cp_commit();
            asm volatile("cp.async.wait_group 1;" ::: "memory");
        } else {
            asm volatile("cp.async.wait_group 0;" ::: "memory");
        }
        __syncthreads();

        uint32_t Ab = sb + bo + 18432;
        uint32_t Bb = sb + bo;
        #pragma unroll
        for (int ky = 0; ky < 3; ky++) {
            #pragma unroll
            for (int kx = 0; kx < 3; kx++) {
                uint32_t a0[4], a1[4];
                {
                    int s0 = xx[0] + kx;
                    uint32_t ao = Ab + (uint32_t)(yrel[0] + ky) * 2048 + (uint32_t)s0 * 32
                                  + (kh16 ^ (uint32_t)((s0 & 4) << 2));
                    ldsm4(a0, ao);
                    int s1 = xx[1] + kx;
                    uint32_t ao1 = Ab + (uint32_t)(yrel[1] + ky) * 2048 + (uint32_t)s1 * 32
                                   + (kh16 ^ (uint32_t)((s1 & 4) << 2));
                    ldsm4(a1, ao1);
                }
                uint32_t b0a = Bb + (uint32_t)(ky * 3 + kx) * 2048 + (uint32_t)oc_lane * 32 + bsw;
                #pragma unroll
                for (int np = 0; np < 4; np++) {
                    uint32_t bh[4];
                    ldsm4(bh, b0a + np * 512);
                    mma(acc[np][0][0], a0, bh[0], bh[1]);
                    mma(acc[np][0][1], a1, bh[0], bh[1]);
                    mma(acc[np][1][0], a0, bh[2], bh[3]);
                    mma(acc[np][1][1], a1, bh[2], bh[3]);
                }
            }
        }
        __syncthreads();
    }

    float* s_out = reinterpret_cast<float*>(smem);
    int prow = lane >> 2, pcol = (lane & 3) * 2;
    #pragma unroll
    for (int np = 0; np < 4; np++)
        #pragma unroll
        for (int nt = 0; nt < 2; nt++)
            #pragma unroll
            for (int m = 0; m < 2; m++)
                #pragma unroll
                for (int r = 0; r < 4; r++) {
                    int oc = np * 16 + nt * 8 + pcol + (r & 1);
                    int px = warp * 32 + m * 16 + prow + ((r >> 1) & 1) * 8;
                    s_out[oc * 257 + px] = acc[np][nt][m][r];
                }
    __syncthreads();
    int lim = NPX - p0;
    for (int i = t; i < 16384; i += 256) {
        int oc = i >> 8, px = i & 255;
        if (px < lim) {
            float v = s_out[oc * 257 + px] + bias[ocq * 64 + oc];
            out[((size_t)b * 256 + ocq * 64 + oc) * NPX + p0 + px] = v;
        }
    }
}

// ---------------------------------------------------------------------------
extern "C" void kernel_launch(void* const* d_in, const int* in_sizes, int n_in,
                              void* d_out, int out_size) {
    const float* inputs = (const float*)d_in[0];   // [32,256,56,56]
    const float* se     = (const float*)d_in[1];   // [32,64]
    const float* weight = (const float*)d_in[2];   // [589824,64]
    const float* bias   = (const float*)d_in[3];   // [256]
    float* out = (float*)d_out;

    cudaFuncSetAttribute(synth_kernel, cudaFuncAttributeMaxDynamicSharedMemorySize, SY_TOTAL);
    cudaFuncSetAttribute(xprep_kernel, cudaFuncAttributeMaxDynamicSharedMemorySize, 57344);
    cudaFuncSetAttribute(conv_kernel, cudaFuncAttributeMaxDynamicSharedMemorySize, SMEM_TOTAL);

    synth_kernel<<<2304, 256, SY_TOTAL>>>(se, weight);
    xprep_kernel<<<dim3(58, Bn), 256, 57344>>>(inputs);
    conv_kernel<<<dim3(13, 4, Bn), 256, SMEM_TOTAL>>>(bias, out);
}

// round 14
// speedup vs baseline: 1.1550x; 1.1550x over previous
#include <cuda_runtime.h>
#include <cuda_fp16.h>
#include <cstdint>

#define Bn 32
#define HWn 56
#define NPX 3136

// staged weights: [b][ocg2][chunk16] blocks of [tap9][ocl128][icl16] fp16 (iclS swizzled)
__device__ __half g_wH[(size_t)Bn * 2 * 16 * 18432];
// staged input: [b][yslot58][xslot64][ic256] fp16, zero-padded borders, ic^8 swizzle per xslot&4
__device__ __half g_xH[(size_t)Bn * 58 * 64 * 256];

static __device__ __forceinline__ uint32_t smem_u32(const void* p) {
    uint32_t a;
    asm("{ .reg .u64 t; cvta.to.shared.u64 t, %1; cvt.u32.u64 %0, t; }" : "=r"(a) : "l"(p));
    return a;
}
static __device__ __forceinline__ void cp16(uint32_t dst, const void* src) {
    asm volatile("cp.async.cg.shared.global [%0], [%1], 16;" :: "r"(dst), "l"(src));
}
static __device__ __forceinline__ void cp_commit() {
    asm volatile("cp.async.commit_group;" ::: "memory");
}
static __device__ __forceinline__ void ldsm4(uint32_t* r, uint32_t a) {
    asm volatile("ldmatrix.sync.aligned.m8n8.x4.shared.b16 {%0,%1,%2,%3}, [%4];"
                 : "=r"(r[0]), "=r"(r[1]), "=r"(r[2]), "=r"(r[3]) : "r"(a));
}
static __device__ __forceinline__ void mma(float* c, const uint32_t* a, uint32_t b0, uint32_t b1) {
    asm volatile("mma.sync.aligned.m16n8k16.row.col.f32.f16.f16.f32 "
                 "{%0,%1,%2,%3}, {%4,%5,%6,%7}, {%8,%9}, {%0,%1,%2,%3};"
                 : "+f"(c[0]), "+f"(c[1]), "+f"(c[2]), "+f"(c[3])
                 : "r"(a[0]), "r"(a[1]), "r"(a[2]), "r"(a[3]), "r"(b0), "r"(b1));
}

// ---------------------------------------------------------------------------
// Kernel 1: weight synthesis as split-fp16 MMA GEMM, A fragments loaded
// DIRECTLY from global (no smem staging, no LDSM-A, one sync total).
// Block (tap, ocl_hi, chunk, ocg): M=256 Wt rows x K=64 x N=32 batches.
// hi = fp16(64*v), lo = fp16((64*v - hi)*2048); result = (hi*hi + cross/2048)/64.
// ---------------------------------------------------------------------------
#define SB_HI 0
#define SB_LO 4096
#define S_OUT 8192
#define SY_TOTAL (S_OUT + 20480)   /* 28672 */

__global__ __launch_bounds__(256, 2)
void synth_kernel(const float* __restrict__ se, const float* __restrict__ Wt) {
    extern __shared__ char sy[];
    uint32_t sb = smem_u32(sy);
    unsigned short* s_out16 = reinterpret_cast<unsigned short*>(sy + S_OUT);

    int tid = threadIdx.x, lane = tid & 31, warp = tid >> 5;
    int blk = blockIdx.x;                  // 2304 = 9*8*16*2
    int tap = blk % 9; int tmp = blk / 9;
    int ocl_hi = tmp & 7; tmp >>= 3;
    int chunk = tmp & 15; int ocg = tmp >> 4;

    // --- load se -> B hi/lo smem (swizzled rows of 128B) ---
    {
        int b = tid >> 3, kq = tid & 7;
        float4 v0 = *reinterpret_cast<const float4*>(se + b * 64 + kq * 8);
        float4 v1 = *reinterpret_cast<const float4*>(se + b * 64 + kq * 8 + 4);
        float vv[8] = {v0.x, v0.y, v0.z, v0.w, v1.x, v1.y, v1.z, v1.w};
        unsigned short hs[8], ls[8];
        #pragma unroll
        for (int j = 0; j < 8; j++) {
            __half h = __float2half_rn(vv[j]);
            float r = (vv[j] - __half2float(h)) * 2048.f;
            hs[j] = __half_as_ushort(h);
            ls[j] = __half_as_ushort(__float2half_rn(r));
        }
        uint32_t addr = (uint32_t)b * 128 + (uint32_t)((kq ^ (b & 7)) * 16);
        *reinterpret_cast<uint4*>(sy + SB_HI + addr) = make_uint4(
            (uint32_t)hs[0] | ((uint32_t)hs[1] << 16), (uint32_t)hs[2] | ((uint32_t)hs[3] << 16),
            (uint32_t)hs[4] | ((uint32_t)hs[5] << 16), (uint32_t)hs[6] | ((uint32_t)hs[7] << 16));
        *reinterpret_cast<uint4*>(sy + SB_LO + addr) = make_uint4(
            (uint32_t)ls[0] | ((uint32_t)ls[1] << 16), (uint32_t)ls[2] | ((uint32_t)ls[3] << 16),
            (uint32_t)ls[4] | ((uint32_t)ls[5] << 16), (uint32_t)ls[6] | ((uint32_t)ls[7] << 16));
    }
    __syncthreads();

    int r0 = lane >> 2, c0 = (lane & 3) * 2;
    int b_bl = (lane & 7) + ((lane >> 4) & 1) * 8;
    int b_kh = (lane >> 3) & 1;
    const float SC = 4.8828125e-4f, INV = 1.f / 64.f;

    #pragma unroll 1
    for (int q = 0; q < 2; q++) {
        int mt = warp * 2 + q;                         // m-tile 0..15

        // two row base pointers (r0, r0+8 within m-tile)
        const float* rowp[2];
        #pragma unroll
        for (int h = 0; h < 2; h++) {
            int r = mt * 16 + r0 + h * 8;
            size_t o = ((size_t)(ocg * 128 + ocl_hi * 16 + (r >> 4)) * 256
                        + chunk * 16 + (r & 15)) * 9 + tap;
            rowp[h] = Wt + o * 64;
        }

        // burst: 16 independent float2 loads (A fragments, all kt)
        float2 src[16];
        #pragma unroll
        for (int kt = 0; kt < 4; kt++)
            #pragma unroll
            for (int j = 0; j < 4; j++)
                src[kt * 4 + j] = *reinterpret_cast<const float2*>(
                    rowp[j & 1] + kt * 16 + c0 + (j >> 1) * 8);

        // convert: hi = fp16(64v), lo = fp16((64v - hi)*2048)
        uint32_t Ah[16], Al[16];
        #pragma unroll
        for (int i = 0; i < 16; i++) {
            float sx = src[i].x * 64.f, sz = src[i].y * 64.f;
            __half2 h2 = __floats2half2_rn(sx, sz);
            float2 hf = __half22float2(h2);
            __half2 l2 = __floats2half2_rn((sx - hf.x) * 2048.f, (sz - hf.y) * 2048.f);
            Ah[i] = *reinterpret_cast<uint32_t*>(&h2);
            Al[i] = *reinterpret_cast<uint32_t*>(&l2);
        }

        float acc1[4][4], acc2[4][4];
        #pragma unroll
        for (int n = 0; n < 4; n++)
            #pragma unroll
            for (int k = 0; k < 4; k++) { acc1[n][k] = 0.f; acc2[n][k] = 0.f; }

        #pragma unroll
        for (int kt = 0; kt < 4; kt++) {
            uint32_t Bh[2][4], Bl[2][4];
            #pragma unroll
            for (int pr = 0; pr < 2; pr++) {
                int bl = b_bl + pr * 16;
                uint32_t baddr = (uint32_t)bl * 128 + (uint32_t)(((kt * 2 + b_kh) ^ (bl & 7)) * 16);
                ldsm4(Bh[pr], sb + SB_HI + baddr);
                ldsm4(Bl[pr], sb + SB_LO + baddr);
            }
            #pragma unroll
            for (int pr = 0; pr < 2; pr++)
                #pragma unroll
                for (int sub = 0; sub < 2; sub++) {
                    int nt = pr * 2 + sub;
                    mma(acc1[nt], &Ah[kt * 4], Bh[pr][sub * 2], Bh[pr][sub * 2 + 1]);
                    mma(acc2[nt], &Ah[kt * 4], Bl[pr][sub * 2], Bl[pr][sub * 2 + 1]);
                    mma(acc2[nt], &Al[kt * 4], Bh[pr][sub * 2], Bh[pr][sub * 2 + 1]);
                }
        }

        #pragma unroll
        for (int nt = 0; nt < 4; nt++) {
            float v0 = (acc1[nt][0] + acc2[nt][0] * SC) * INV;
            float v1 = (acc1[nt][1] + acc2[nt][1] * SC) * INV;
            float v2 = (acc1[nt][2] + acc2[nt][2] * SC) * INV;
            float v3 = (acc1[nt][3] + acc2[nt][3] * SC) * INV;
            uint32_t p01 = (uint32_t)__half_as_ushort(__float2half_rn(v0))
                         | ((uint32_t)__half_as_ushort(__float2half_rn(v1)) << 16);
            uint32_t p23 = (uint32_t)__half_as_ushort(__float2half_rn(v2))
                         | ((uint32_t)__half_as_ushort(__float2half_rn(v3)) << 16);
            int m0 = mt * 16 + (lane >> 2);
            int bc = nt * 8 + (lane & 3) * 2;
            *reinterpret_cast<uint32_t*>(&s_out16[m0 * 40 + bc]) = p01;
            *reinterpret_cast<uint32_t*>(&s_out16[(m0 + 8) * 40 + bc]) = p23;
        }
    }
    __syncthreads();

    // --- flush: per b, 512B contiguous dest chunk; gathered STG.64 ---
    size_t inner = (size_t)tap * 2048 + (size_t)ocl_hi * 256;
    for (int i = tid; i < 2048; i += 256) {
        int b = i >> 6, d4 = (i & 63) * 4;
        int ocl = d4 >> 4;
        int xorm = (ocl & 4) ? 8 : 0;
        unsigned short w[4];
        #pragma unroll
        for (int j = 0; j < 4; j++) {
            int icl = ((d4 + j) & 15) ^ xorm;
            w[j] = s_out16[(ocl * 16 + icl) * 40 + b];
        }
        size_t blko = ((size_t)(b * 2 + ocg) * 16 + chunk) * 18432;
        *reinterpret_cast<uint2*>(&reinterpret_cast<unsigned short*>(g_wH)[blko + inner + d4]) =
            make_uint2((uint32_t)w[0] | ((uint32_t)w[1] << 16),
                       (uint32_t)w[2] | ((uint32_t)w[3] << 16));
    }
}

// ---------------------------------------------------------------------------
// Kernel 2: input transpose to [b][yslot][xslot][ic] fp16, padded + swizzled
// ---------------------------------------------------------------------------
__global__ __launch_bounds__(256)
void xprep_kernel(const float* __restrict__ in) {
    extern __shared__ float s[];                     // [256][56]
    int ys = blockIdx.x, b = blockIdx.y, t = threadIdx.x;
    size_t obase = ((size_t)b * 58 + ys) * 64 * 256;

    if (ys == 0 || ys == 57) {
        uint4 z = make_uint4(0, 0, 0, 0);
        uint4* ph = reinterpret_cast<uint4*>(g_xH + obase);
        for (int i = t; i < 2048; i += 256) ph[i] = z;
        return;
    }
    int y = ys - 1;
    for (int i = t; i < 256 * 56; i += 256) {
        int ic = i / 56, x = i - ic * 56;
        s[i] = in[((size_t)b * 256 + ic) * NPX + y * 56 + x];
    }
    __syncthreads();

    int xs = t >> 2, icq = t & 3;
    bool real = (xs >= 1 && xs <= 56);
    int xsw = (xs & 4) ? 8 : 0;
    #pragma unroll
    for (int g = 0; g < 8; g++) {
        unsigned short hs[8];
        #pragma unroll
        for (int j = 0; j < 8; j++) {
            int ic_out = icq * 64 + g * 8 + j;
            int src_ic = ic_out ^ xsw;
            float v = real ? s[src_ic * 56 + (xs - 1)] : 0.f;
            hs[j] = __half_as_ushort(__float2half_rn(v));
        }
        size_t eo = obase + (size_t)xs * 256 + icq * 64 + g * 8;
        *reinterpret_cast<uint4*>(g_xH + eo) = make_uint4(
            (uint32_t)hs[0] | ((uint32_t)hs[1] << 16), (uint32_t)hs[2] | ((uint32_t)hs[3] << 16),
            (uint32_t)hs[4] | ((uint32_t)hs[5] << 16), (uint32_t)hs[6] | ((uint32_t)hs[7] << 16));
    }
}

// ---------------------------------------------------------------------------
// Kernel 3: implicit-GEMM conv, fp16 mma.sync, m32-per-warp / oc64-per-CTA.
// grid (13 pxtile256, 4 ocq, 32 b), 256 threads, 2 CTAs/SM.  (unchanged)
// ---------------------------------------------------------------------------
#define BUFB 34816
#define SMEM_TOTAL (2 * BUFB)   /* 69632 */

__global__ __launch_bounds__(256, 2)
void conv_kernel(const float* __restrict__ bias, float* __restrict__ out) {
    extern __shared__ char smem[];
    uint32_t sb = smem_u32(smem);
    int t = threadIdx.x, warp = t >> 5, lane = t & 31;
    int tile = blockIdx.x, ocq = blockIdx.y, b = blockIdx.z;
    int ocg = ocq >> 1, ohalf = ocq & 1;
    int p0 = tile * 256;
    int base = p0 / 56; if (base > 50) base = 50;

    int lrow = (lane & 7) + ((lane >> 3) & 1) * 8;
    uint32_t kh16 = (uint32_t)(lane >> 4) * 16;
    int xx[2], yrel[2];
    #pragma unroll
    for (int m = 0; m < 2; m++) {
        int pixel = p0 + warp * 32 + m * 16 + lrow;
        if (pixel >= NPX) pixel = p0;
        int yy = pixel / 56;
        xx[m] = pixel - yy * 56;
        yrel[m] = yy - base;
    }
    int oc_lane = (lane & 7) + ((lane >> 4) & 1) * 8;
    uint32_t bsw = ((uint32_t)((lane >> 3) & 1) * 16) ^ (uint32_t)((oc_lane & 4) << 2);

    const char* wsrc = (const char*)g_wH + ((size_t)(b * 2 + ocg) * 16) * 36864;
    const char* xh0 = (const char*)g_xH + ((size_t)b * 58 + base) * 32768;

    float acc[4][2][2][4];
    #pragma unroll
    for (int i = 0; i < 4; i++)
        #pragma unroll
        for (int j = 0; j < 2; j++)
            #pragma unroll
            for (int m = 0; m < 2; m++)
                #pragma unroll
                for (int k = 0; k < 4; k++) acc[i][j][m][k] = 0.f;

    auto stage = [&](int c, uint32_t bo) {
        const char* wb = wsrc + (size_t)c * 36864;
        for (int i = t; i < 1152; i += 256) {
            int tap = i >> 7, off = i & 127;
            cp16(sb + bo + tap * 2048 + off * 16,
                 wb + tap * 4096 + ohalf * 2048 + off * 16);
        }
        for (int i = t; i < 1024; i += 256) {
            int slot = i >> 7, j = i & 127, xs = j >> 1, half = j & 1;
            cp16(sb + bo + 18432 + slot * 2048 + xs * 32 + half * 16,
                 xh0 + (size_t)slot * 32768 + xs * 512 + c * 32 + half * 16);
        }
    };

    stage(0, 0);
    cp_commit();

    for (int c = 0; c < 16; c++) {
        uint32_t bo = (uint32_t)(c & 1) * BUFB;
        if (c < 15) {
            stage(c + 1, (uint32_t)((c + 1) & 1) * BUFB);
            cp_commit();
            asm volatile("cp.async.wait_group 1;" ::: "memory");
        } else {
            asm volatile("cp.async.wait_group 0;" ::: "memory");
        }
        __syncthreads();

        uint32_t Ab = sb + bo + 18432;
        uint32_t Bb = sb + bo;
        #pragma unroll
        for (int ky = 0; ky < 3; ky++) {
            #pragma unroll
            for (int kx = 0; kx < 3; kx++) {
                uint32_t a0[4], a1[4];
                {
                    int s0 = xx[0] + kx;
                    uint32_t ao = Ab + (uint32_t)(yrel[0] + ky) * 2048 + (uint32_t)s0 * 32
                                  + (kh16 ^ (uint32_t)((s0 & 4) << 2));
                    ldsm4(a0, ao);
                    int s1 = xx[1] + kx;
                    uint32_t ao1 = Ab + (uint32_t)(yrel[1] + ky) * 2048 + (uint32_t)s1 * 32
                                   + (kh16 ^ (uint32_t)((s1 & 4) << 2));
                    ldsm4(a1, ao1);
                }
                uint32_t b0a = Bb + (uint32_t)(ky * 3 + kx) * 2048 + (uint32_t)oc_lane * 32 + bsw;
                #pragma unroll
                for (int np = 0; np < 4; np++) {
                    uint32_t bh[4];
                    ldsm4(bh, b0a + np * 512);
                    mma(acc[np][0][0], a0, bh[0], bh[1]);
                    mma(acc[np][0][1], a1, bh[0], bh[1]);
                    mma(acc[np][1][0], a0, bh[2], bh[3]);
                    mma(acc[np][1][1], a1, bh[2], bh[3]);
                }
            }
        }
        __syncthreads();
    }

    float* s_out = reinterpret_cast<float*>(smem);
    int prow = lane >> 2, pcol = (lane & 3) * 2;
    #pragma unroll
    for (int np = 0; np < 4; np++)
        #pragma unroll
        for (int nt = 0; nt < 2; nt++)
            #pragma unroll
            for (int m = 0; m < 2; m++)
                #pragma unroll
                for (int r = 0; r < 4; r++) {
                    int oc = np * 16 + nt * 8 + pcol + (r & 1);
                    int px = warp * 32 + m * 16 + prow + ((r >> 1) & 1) * 8;
                    s_out[oc * 257 + px] = acc[np][nt][m][r];
                }
    __syncthreads();
    int lim = NPX - p0;
    for (int i = t; i < 16384; i += 256) {
        int oc = i >> 8, px = i & 255;
        if (px < lim) {
            float v = s_out[oc * 257 + px] + bias[ocq * 64 + oc];
            out[((size_t)b * 256 + ocq * 64 + oc) * NPX + p0 + px] = v;
        }
    }
}

// ---------------------------------------------------------------------------
extern "C" void kernel_launch(void* const* d_in, const int* in_sizes, int n_in,
                              void* d_out, int out_size) {
    const float* inputs = (const float*)d_in[0];   // [32,256,56,56]
    const float* se     = (const float*)d_in[1];   // [32,64]
    const float* weight = (const float*)d_in[2];   // [589824,64]
    const float* bias   = (const float*)d_in[3];   // [256]
    float* out = (float*)d_out;

    cudaFuncSetAttribute(synth_kernel, cudaFuncAttributeMaxDynamicSharedMemorySize, SY_TOTAL);
    cudaFuncSetAttribute(xprep_kernel, cudaFuncAttributeMaxDynamicSharedMemorySize, 57344);
    cudaFuncSetAttribute(conv_kernel, cudaFuncAttributeMaxDynamicSharedMemorySize, SMEM_TOTAL);

    synth_kernel<<<2304, 256, SY_TOTAL>>>(se, weight);
    xprep_kernel<<<dim3(58, Bn), 256, 57344>>>(inputs);
    conv_kernel<<<dim3(13, 4, Bn), 256, SMEM_TOTAL>>>(bias, out);
}

// round 16
// speedup vs baseline: 1.1592x; 1.0036x over previous
#include <cuda_runtime.h>
#include <cuda_fp16.h>
#include <cstdint>

#define Bn 32
#define HWn 56
#define NPX 3136

// staged weights: [b][ocg2][chunk16] blocks of [tap9][ocl128][icl16] fp16 (iclS swizzled)
__device__ __half g_wH[(size_t)Bn * 2 * 16 * 18432];
// staged input: [b][yslot58][xslot64][ic256] fp16, zero-padded borders, ic^8 swizzle per xslot&4
__device__ __half g_xH[(size_t)Bn * 58 * 64 * 256];

static __device__ __forceinline__ uint32_t smem_u32(const void* p) {
    uint32_t a;
    asm("{ .reg .u64 t; cvta.to.shared.u64 t, %1; cvt.u32.u64 %0, t; }" : "=r"(a) : "l"(p));
    return a;
}
static __device__ __forceinline__ void cp16(uint32_t dst, const void* src) {
    asm volatile("cp.async.cg.shared.global [%0], [%1], 16;" :: "r"(dst), "l"(src));
}
static __device__ __forceinline__ void cp_commit() {
    asm volatile("cp.async.commit_group;" ::: "memory");
}
static __device__ __forceinline__ void ldsm4(uint32_t* r, uint32_t a) {
    asm volatile("ldmatrix.sync.aligned.m8n8.x4.shared.b16 {%0,%1,%2,%3}, [%4];"
                 : "=r"(r[0]), "=r"(r[1]), "=r"(r[2]), "=r"(r[3]) : "r"(a));
}
static __device__ __forceinline__ void mma(float* c, const uint32_t* a, uint32_t b0, uint32_t b1) {
    asm volatile("mma.sync.aligned.m16n8k16.row.col.f32.f16.f16.f32 "
                 "{%0,%1,%2,%3}, {%4,%5,%6,%7}, {%8,%9}, {%0,%1,%2,%3};"
                 : "+f"(c[0]), "+f"(c[1]), "+f"(c[2]), "+f"(c[3])
                 : "r"(a[0]), "r"(a[1]), "r"(a[2]), "r"(a[3]), "r"(b0), "r"(b1));
}

// ---------------------------------------------------------------------------
// Kernel 1: weight synthesis as split-fp16 MMA GEMM, A fragments loaded
// directly from global. (unchanged from round 14)
// ---------------------------------------------------------------------------
#define SB_HI 0
#define SB_LO 4096
#define S_OUT 8192
#define SY_TOTAL (S_OUT + 20480)   /* 28672 */

__global__ __launch_bounds__(256, 2)
void synth_kernel(const float* __restrict__ se, const float* __restrict__ Wt) {
    extern __shared__ char sy[];
    uint32_t sb = smem_u32(sy);
    unsigned short* s_out16 = reinterpret_cast<unsigned short*>(sy + S_OUT);

    int tid = threadIdx.x, lane = tid & 31, warp = tid >> 5;
    int blk = blockIdx.x;                  // 2304 = 9*8*16*2
    int tap = blk % 9; int tmp = blk / 9;
    int ocl_hi = tmp & 7; tmp >>= 3;
    int chunk = tmp & 15; int ocg = tmp >> 4;

    {
        int b = tid >> 3, kq = tid & 7;
        float4 v0 = *reinterpret_cast<const float4*>(se + b * 64 + kq * 8);
        float4 v1 = *reinterpret_cast<const float4*>(se + b * 64 + kq * 8 + 4);
        float vv[8] = {v0.x, v0.y, v0.z, v0.w, v1.x, v1.y, v1.z, v1.w};
        unsigned short hs[8], ls[8];
        #pragma unroll
        for (int j = 0; j < 8; j++) {
            __half h = __float2half_rn(vv[j]);
            float r = (vv[j] - __half2float(h)) * 2048.f;
            hs[j] = __half_as_ushort(h);
            ls[j] = __half_as_ushort(__float2half_rn(r));
        }
        uint32_t addr = (uint32_t)b * 128 + (uint32_t)((kq ^ (b & 7)) * 16);
        *reinterpret_cast<uint4*>(sy + SB_HI + addr) = make_uint4(
            (uint32_t)hs[0] | ((uint32_t)hs[1] << 16), (uint32_t)hs[2] | ((uint32_t)hs[3] << 16),
            (uint32_t)hs[4] | ((uint32_t)hs[5] << 16), (uint32_t)hs[6] | ((uint32_t)hs[7] << 16));
        *reinterpret_cast<uint4*>(sy + SB_LO + addr) = make_uint4(
            (uint32_t)ls[0] | ((uint32_t)ls[1] << 16), (uint32_t)ls[2] | ((uint32_t)ls[3] << 16),
            (uint32_t)ls[4] | ((uint32_t)ls[5] << 16), (uint32_t)ls[6] | ((uint32_t)ls[7] << 16));
    }
    __syncthreads();

    int r0 = lane >> 2, c0 = (lane & 3) * 2;
    int b_bl = (lane & 7) + ((lane >> 4) & 1) * 8;
    int b_kh = (lane >> 3) & 1;
    const float SC = 4.8828125e-4f, INV = 1.f / 64.f;

    #pragma unroll 1
    for (int q = 0; q < 2; q++) {
        int mt = warp * 2 + q;

        const float* rowp[2];
        #pragma unroll
        for (int h = 0; h < 2; h++) {
            int r = mt * 16 + r0 + h * 8;
            size_t o = ((size_t)(ocg * 128 + ocl_hi * 16 + (r >> 4)) * 256
                        + chunk * 16 + (r & 15)) * 9 + tap;
            rowp[h] = Wt + o * 64;
        }

        float2 src[16];
        #pragma unroll
        for (int kt = 0; kt < 4; kt++)
            #pragma unroll
            for (int j = 0; j < 4; j++)
                src[kt * 4 + j] = *reinterpret_cast<const float2*>(
                    rowp[j & 1] + kt * 16 + c0 + (j >> 1) * 8);

        uint32_t Ah[16], Al[16];
        #pragma unroll
        for (int i = 0; i < 16; i++) {
            float sx = src[i].x * 64.f, sz = src[i].y * 64.f;
            __half2 h2 = __floats2half2_rn(sx, sz);
            float2 hf = __half22float2(h2);
            __half2 l2 = __floats2half2_rn((sx - hf.x) * 2048.f, (sz - hf.y) * 2048.f);
            Ah[i] = *reinterpret_cast<uint32_t*>(&h2);
            Al[i] = *reinterpret_cast<uint32_t*>(&l2);
        }

        float acc1[4][4], acc2[4][4];
        #pragma unroll
        for (int n = 0; n < 4; n++)
            #pragma unroll
            for (int k = 0; k < 4; k++) { acc1[n][k] = 0.f; acc2[n][k] = 0.f; }

        #pragma unroll
        for (int kt = 0; kt < 4; kt++) {
            uint32_t Bh[2][4], Bl[2][4];
            #pragma unroll
            for (int pr = 0; pr < 2; pr++) {
                int bl = b_bl + pr * 16;
                uint32_t baddr = (uint32_t)bl * 128 + (uint32_t)(((kt * 2 + b_kh) ^ (bl & 7)) * 16);
                ldsm4(Bh[pr], sb + SB_HI + baddr);
                ldsm4(Bl[pr], sb + SB_LO + baddr);
            }
            #pragma unroll
            for (int pr = 0; pr < 2; pr++)
                #pragma unroll
                for (int sub = 0; sub < 2; sub++) {
                    int nt = pr * 2 + sub;
                    mma(acc1[nt], &Ah[kt * 4], Bh[pr][sub * 2], Bh[pr][sub * 2 + 1]);
                    mma(acc2[nt], &Ah[kt * 4], Bl[pr][sub * 2], Bl[pr][sub * 2 + 1]);
                    mma(acc2[nt], &Al[kt * 4], Bh[pr][sub * 2], Bh[pr][sub * 2 + 1]);
                }
        }

        #pragma unroll
        for (int nt = 0; nt < 4; nt++) {
            float v0 = (acc1[nt][0] + acc2[nt][0] * SC) * INV;
            float v1 = (acc1[nt][1] + acc2[nt][1] * SC) * INV;
            float v2 = (acc1[nt][2] + acc2[nt][2] * SC) * INV;
            float v3 = (acc1[nt][3] + acc2[nt][3] * SC) * INV;
            uint32_t p01 = (uint32_t)__half_as_ushort(__float2half_rn(v0))
                         | ((uint32_t)__half_as_ushort(__float2half_rn(v1)) << 16);
            uint32_t p23 = (uint32_t)__half_as_ushort(__float2half_rn(v2))
                         | ((uint32_t)__half_as_ushort(__float2half_rn(v3)) << 16);
            int m0 = mt * 16 + (lane >> 2);
            int bc = nt * 8 + (lane & 3) * 2;
            *reinterpret_cast<uint32_t*>(&s_out16[m0 * 40 + bc]) = p01;
            *reinterpret_cast<uint32_t*>(&s_out16[(m0 + 8) * 40 + bc]) = p23;
        }
    }
    __syncthreads();

    size_t inner = (size_t)tap * 2048 + (size_t)ocl_hi * 256;
    for (int i = tid; i < 2048; i += 256) {
        int b = i >> 6, d4 = (i & 63) * 4;
        int ocl = d4 >> 4;
        int xorm = (ocl & 4) ? 8 : 0;
        unsigned short w[4];
        #pragma unroll
        for (int j = 0; j < 4; j++) {
            int icl = ((d4 + j) & 15) ^ xorm;
            w[j] = s_out16[(ocl * 16 + icl) * 40 + b];
        }
        size_t blko = ((size_t)(b * 2 + ocg) * 16 + chunk) * 18432;
        *reinterpret_cast<uint2*>(&reinterpret_cast<unsigned short*>(g_wH)[blko + inner + d4]) =
            make_uint2((uint32_t)w[0] | ((uint32_t)w[1] << 16),
                       (uint32_t)w[2] | ((uint32_t)w[3] << 16));
    }
}

// ---------------------------------------------------------------------------
// Kernel 2: input transpose to [b][yslot][xslot][ic] fp16, padded + swizzled
// ---------------------------------------------------------------------------
__global__ __launch_bounds__(256)
void xprep_kernel(const float* __restrict__ in) {
    extern __shared__ float s[];                     // [256][56]
    int ys = blockIdx.x, b = blockIdx.y, t = threadIdx.x;
    size_t obase = ((size_t)b * 58 + ys) * 64 * 256;

    if (ys == 0 || ys == 57) {
        uint4 z = make_uint4(0, 0, 0, 0);
        uint4* ph = reinterpret_cast<uint4*>(g_xH + obase);
        for (int i = t; i < 2048; i += 256) ph[i] = z;
        return;
    }
    int y = ys - 1;
    for (int i = t; i < 256 * 56; i += 256) {
        int ic = i / 56, x = i - ic * 56;
        s[i] = in[((size_t)b * 256 + ic) * NPX + y * 56 + x];
    }
    __syncthreads();

    int xs = t >> 2, icq = t & 3;
    bool real = (xs >= 1 && xs <= 56);
    int xsw = (xs & 4) ? 8 : 0;
    #pragma unroll
    for (int g = 0; g < 8; g++) {
        unsigned short hs[8];
        #pragma unroll
        for (int j = 0; j < 8; j++) {
            int ic_out = icq * 64 + g * 8 + j;
            int src_ic = ic_out ^ xsw;
            float v = real ? s[src_ic * 56 + (xs - 1)] : 0.f;
            hs[j] = __half_as_ushort(__float2half_rn(v));
        }
        size_t eo = obase + (size_t)xs * 256 + icq * 64 + g * 8;
        *reinterpret_cast<uint4*>(g_xH + eo) = make_uint4(
            (uint32_t)hs[0] | ((uint32_t)hs[1] << 16), (uint32_t)hs[2] | ((uint32_t)hs[3] << 16),
            (uint32_t)hs[4] | ((uint32_t)hs[5] << 16), (uint32_t)hs[6] | ((uint32_t)hs[7] << 16));
    }
}

// ---------------------------------------------------------------------------
// Kernel 3: implicit-GEMM conv, fp16 mma.sync, m32-per-warp / oc64-per-CTA.
// 3-stage cp.async pipeline, ONE __syncthreads per chunk:
//   wait(stage c) -> sync -> compute(c) -> issue(c+2)
// grid (13 pxtile256, 4 ocq, 32 b), 256 threads, 2 CTAs/SM.
// ---------------------------------------------------------------------------
#define BUFB 34816
#define NSTAGE 3
#define SMEM_TOTAL (NSTAGE * BUFB)   /* 104448 */

__global__ __launch_bounds__(256, 2)
void conv_kernel(const float* __restrict__ bias, float* __restrict__ out) {
    extern __shared__ char smem[];
    uint32_t sb = smem_u32(smem);
    int t = threadIdx.x, warp = t >> 5, lane = t & 31;
    int tile = blockIdx.x, ocq = blockIdx.y, b = blockIdx.z;
    int ocg = ocq >> 1, ohalf = ocq & 1;
    int p0 = tile * 256;
    int base = p0 / 56; if (base > 50) base = 50;

    int lrow = (lane & 7) + ((lane >> 3) & 1) * 8;
    uint32_t kh16 = (uint32_t)(lane >> 4) * 16;
    int xx[2], yrel[2];
    #pragma unroll
    for (int m = 0; m < 2; m++) {
        int pixel = p0 + warp * 32 + m * 16 + lrow;
        if (pixel >= NPX) pixel = p0;
        int yy = pixel / 56;
        xx[m] = pixel - yy * 56;
        yrel[m] = yy - base;
    }
    int oc_lane = (lane & 7) + ((lane >> 4) & 1) * 8;
    uint32_t bsw = ((uint32_t)((lane >> 3) & 1) * 16) ^ (uint32_t)((oc_lane & 4) << 2);

    const char* wsrc = (const char*)g_wH + ((size_t)(b * 2 + ocg) * 16) * 36864;
    const char* xh0 = (const char*)g_xH + ((size_t)b * 58 + base) * 32768;

    float acc[4][2][2][4];
    #pragma unroll
    for (int i = 0; i < 4; i++)
        #pragma unroll
        for (int j = 0; j < 2; j++)
            #pragma unroll
            for (int m = 0; m < 2; m++)
                #pragma unroll
                for (int k = 0; k < 4; k++) acc[i][j][m][k] = 0.f;

    auto stage = [&](int c, uint32_t bo) {
        const char* wb = wsrc + (size_t)c * 36864;
        for (int i = t; i < 1152; i += 256) {
            int tap = i >> 7, off = i & 127;
            cp16(sb + bo + tap * 2048 + off * 16,
                 wb + tap * 4096 + ohalf * 2048 + off * 16);
        }
        for (int i = t; i < 1024; i += 256) {
            int slot = i >> 7, j = i & 127, xs = j >> 1, half = j & 1;
            cp16(sb + bo + 18432 + slot * 2048 + xs * 32 + half * 16,
                 xh0 + (size_t)slot * 32768 + xs * 512 + c * 32 + half * 16);
        }
    };

    stage(0, 0); cp_commit();
    stage(1, BUFB); cp_commit();

    for (int c = 0; c < 16; c++) {
        if (c < 15) {
            asm volatile("cp.async.wait_group 1;" ::: "memory");
        } else {
            asm volatile("cp.async.wait_group 0;" ::: "memory");
        }
        __syncthreads();

        uint32_t bo = (uint32_t)(c % NSTAGE) * BUFB;
        uint32_t Ab = sb + bo + 18432;
        uint32_t Bb = sb + bo;
        #pragma unroll
        for (int ky = 0; ky < 3; ky++) {
            #pragma unroll
            for (int kx = 0; kx < 3; kx++) {
                uint32_t a0[4], a1[4];
                {
                    int s0 = xx[0] + kx;
                    uint32_t ao = Ab + (uint32_t)(yrel[0] + ky) * 2048 + (uint32_t)s0 * 32
                                  + (kh16 ^ (uint32_t)((s0 & 4) << 2));
                    ldsm4(a0, ao);
                    int s1 = xx[1] + kx;
                    uint32_t ao1 = Ab + (uint32_t)(yrel[1] + ky) * 2048 + (uint32_t)s1 * 32
                                   + (kh16 ^ (uint32_t)((s1 & 4) << 2));
                    ldsm4(a1, ao1);
                }
                uint32_t b0a = Bb + (uint32_t)(ky * 3 + kx) * 2048 + (uint32_t)oc_lane * 32 + bsw;
                #pragma unroll
                for (int np = 0; np < 4; np++) {
                    uint32_t bh[4];
                    ldsm4(bh, b0a + np * 512);
                    mma(acc[np][0][0], a0, bh[0], bh[1]);
                    mma(acc[np][0][1], a1, bh[0], bh[1]);
                    mma(acc[np][1][0], a0, bh[2], bh[3]);
                    mma(acc[np][1][1], a1, bh[2], bh[3]);
                }
            }
        }

        if (c + 2 < 16) {
            stage(c + 2, (uint32_t)((c + 2) % NSTAGE) * BUFB);
            cp_commit();
        }
    }
    __syncthreads();   // chunk 15 readers (buf 0) vs epilogue s_out overwrite

    float* s_out = reinterpret_cast<float*>(smem);
    int prow = lane >> 2, pcol = (lane & 3) * 2;
    #pragma unroll
    for (int np = 0; np < 4; np++)
        #pragma unroll
        for (int nt = 0; nt < 2; nt++)
            #pragma unroll
            for (int m = 0; m < 2; m++)
                #pragma unroll
                for (int r = 0; r < 4; r++) {
                    int oc = np * 16 + nt * 8 + pcol + (r & 1);
                    int px = warp * 32 + m * 16 + prow + ((r >> 1) & 1) * 8;
                    s_out[oc * 257 + px] = acc[np][nt][m][r];
                }
    __syncthreads();
    int lim = NPX - p0;
    for (int i = t; i < 16384; i += 256) {
        int oc = i >> 8, px = i & 255;
        if (px < lim) {
            float v = s_out[oc * 257 + px] + bias[ocq * 64 + oc];
            out[((size_t)b * 256 + ocq * 64 + oc) * NPX + p0 + px] = v;
        }
    }
}

// ---------------------------------------------------------------------------
extern "C" void kernel_launch(void* const* d_in, const int* in_sizes, int n_in,
                              void* d_out, int out_size) {
    const float* inputs = (const float*)d_in[0];   // [32,256,56,56]
    const float* se     = (const float*)d_in[1];   // [32,64]
    const float* weight = (const float*)d_in[2];   // [589824,64]
    const float* bias   = (const float*)d_in[3];   // [256]
    float* out = (float*)d_out;

    cudaFuncSetAttribute(synth_kernel, cudaFuncAttributeMaxDynamicSharedMemorySize, SY_TOTAL);
    cudaFuncSetAttribute(xprep_kernel, cudaFuncAttributeMaxDynamicSharedMemorySize, 57344);
    cudaFuncSetAttribute(conv_kernel, cudaFuncAttributeMaxDynamicSharedMemorySize, SMEM_TOTAL);

    synth_kernel<<<2304, 256, SY_TOTAL>>>(se, weight);
    xprep_kernel<<<dim3(58, Bn), 256, 57344>>>(inputs);
    conv_kernel<<<dim3(13, 4, Bn), 256, SMEM_TOTAL>>>(bias, out);
}